// round 14
// baseline (speedup 1.0000x reference)
#include <cuda_runtime.h>
#include <cuda_bf16.h>
#include <cstdint>
#include <math.h>

// NT-Xent loss, B=2048, D=512, N=4096, T=0.5.
// loss = (1/N) * sum_i [ 2 + log( sum_{j != i} exp(sim_ij - 2) ) - sim_{i,partner(i)} ]
// sim = (zn zn^T)/T in [-2,2] => fixed shift 2, single pass, no row max.
// bf16 mma.sync GEMM over UPPER-TRIANGULAR tiles (sim symmetric); each
// off-diagonal tile feeds rowsum[rows] AND rowsum[cols].
// 8 wide K-stages (64 bf16 = 128B/row) double-buffered via cp.async.
// NEW: fragment-level software pipelining (double-buffered ldmatrix regs,
// next-ks LDSM issued before current-ks MMA burst) to hide LDSM latency
// that asm-volatile source ordering otherwise exposes.

#define Bz 2048
#define Nn 4096
#define Dd 512
#define NTILE 528

__device__ __nv_bfloat16 g_znh[Nn * Dd];   // bf16 normalized (4 MB, L2-resident)
__device__ float g_rowsum[Nn];             // sum_{j!=i} exp(sim_ij - 2)
__device__ float g_pos[Nn];                // dot(zn_i, zn_partner)

// ---------------------------------------------------------------------------
// exp(2a-2) on the FMA pipe (no MUFU). 2^y, y=(a-1)*2log2e in [-5.9, 0.1];
// magic-add range reduction + deg-5 poly (rel err ~3e-6).
// ---------------------------------------------------------------------------
__device__ __forceinline__ float exp_sim(float a) {
    float y = fmaf(a, 2.8853900817779268f, -2.8853900817779268f);
    float z = y + 12582912.0f;
    float f = y - (z - 12582912.0f);
    int ei = (__float_as_int(z) + (127 - 0x400000)) << 23;
    float p = fmaf(f, 1.3333558146428443e-3f, 9.6181291076284771e-3f);
    p = fmaf(f, p, 5.5504108664821580e-2f);
    p = fmaf(f, p, 2.4022650695910071e-1f);
    p = fmaf(f, p, 6.9314718055994531e-1f);
    p = fmaf(f, p, 1.0f);
    return p * __int_as_float(ei);
}

// ---------------------------------------------------------------------------
// Kernel 1: row-normalize -> bf16 (round-13 version; 5.6us plateau).
// One warp per two rows, 8 loads in flight. 256 blocks x 256 thr.
// ---------------------------------------------------------------------------
__global__ __launch_bounds__(256) void k_normalize(const float* __restrict__ zi,
                                                   const float* __restrict__ zj,
                                                   float* __restrict__ out) {
    int wid = threadIdx.x >> 5;
    int l = threadIdx.x & 31;
    int rA = blockIdx.x * 16 + wid * 2;
    int rB = rA + 1;
    const float4* sA = (rA < Bz)
        ? reinterpret_cast<const float4*>(zi + (size_t)rA * Dd)
        : reinterpret_cast<const float4*>(zj + (size_t)(rA - Bz) * Dd);
    const float4* sB = (rB < Bz)
        ? reinterpret_cast<const float4*>(zi + (size_t)rB * Dd)
        : reinterpret_cast<const float4*>(zj + (size_t)(rB - Bz) * Dd);
    float4 a0 = sA[l];
    float4 a1 = sA[l + 32];
    float4 a2 = sA[l + 64];
    float4 a3 = sA[l + 96];
    float4 b0 = sB[l];
    float4 b1 = sB[l + 32];
    float4 b2 = sB[l + 64];
    float4 b3 = sB[l + 96];
    float ssA = a0.x * a0.x + a0.y * a0.y + a0.z * a0.z + a0.w * a0.w
              + a1.x * a1.x + a1.y * a1.y + a1.z * a1.z + a1.w * a1.w
              + a2.x * a2.x + a2.y * a2.y + a2.z * a2.z + a2.w * a2.w
              + a3.x * a3.x + a3.y * a3.y + a3.z * a3.z + a3.w * a3.w;
    float ssB = b0.x * b0.x + b0.y * b0.y + b0.z * b0.z + b0.w * b0.w
              + b1.x * b1.x + b1.y * b1.y + b1.z * b1.z + b1.w * b1.w
              + b2.x * b2.x + b2.y * b2.y + b2.z * b2.z + b2.w * b2.w
              + b3.x * b3.x + b3.y * b3.y + b3.z * b3.z + b3.w * b3.w;
#pragma unroll
    for (int o = 16; o > 0; o >>= 1) {
        ssA += __shfl_xor_sync(0xffffffffu, ssA, o);
        ssB += __shfl_xor_sync(0xffffffffu, ssB, o);
    }
    float invA = 1.0f / fmaxf(sqrtf(ssA), 1e-8f);
    float invB = 1.0f / fmaxf(sqrtf(ssB), 1e-8f);
    uint2* dA = reinterpret_cast<uint2*>(g_znh + (size_t)rA * Dd);
    uint2* dB = reinterpret_cast<uint2*>(g_znh + (size_t)rB * Dd);
    __nv_bfloat162 h0, h1; uint2 u;
#define CVT_STORE(dst, idx, v, inv)                                            \
    h0 = __floats2bfloat162_rn((v).x * (inv), (v).y * (inv));                  \
    h1 = __floats2bfloat162_rn((v).z * (inv), (v).w * (inv));                  \
    u.x = *reinterpret_cast<uint32_t*>(&h0);                                   \
    u.y = *reinterpret_cast<uint32_t*>(&h1);                                   \
    (dst)[idx] = u;
    CVT_STORE(dA, l,      a0, invA)
    CVT_STORE(dA, l + 32, a1, invA)
    CVT_STORE(dA, l + 64, a2, invA)
    CVT_STORE(dA, l + 96, a3, invA)
    CVT_STORE(dB, l,      b0, invB)
    CVT_STORE(dB, l + 32, b1, invB)
    CVT_STORE(dB, l + 64, b2, invB)
    CVT_STORE(dB, l + 96, b3, invB)
#undef CVT_STORE
    if (l == 0) { g_rowsum[rA] = 0.0f; g_rowsum[rB] = 0.0f; }
    if (threadIdx.x == 0 && blockIdx.x == 0) out[0] = 0.0f;
}

// ---------------------------------------------------------------------------
// fragment loaders (forceinline; constant buffer index after unroll)
// ---------------------------------------------------------------------------
#define PITCH 144
#define STG_BYTES (128 * PITCH)   // 18432 per operand per stage
#define SMEM_TOTAL (4 * STG_BYTES)

__device__ __forceinline__ void ldsm_a(uint32_t (*fr)[4], uint32_t Ab,
                                       uint32_t aoff, uint32_t kb) {
#pragma unroll
    for (int mt = 0; mt < 4; ++mt)
        asm volatile(
            "ldmatrix.sync.aligned.m8n8.x4.shared.b16 {%0,%1,%2,%3}, [%4];"
            : "=r"(fr[mt][0]), "=r"(fr[mt][1]), "=r"(fr[mt][2]), "=r"(fr[mt][3])
            : "r"(Ab + aoff + (uint32_t)mt * (16u * PITCH) + kb));
}
__device__ __forceinline__ void ldsm_b(uint32_t (*fr)[4], uint32_t Bb,
                                       uint32_t boff, uint32_t kb) {
#pragma unroll
    for (int ng = 0; ng < 2; ++ng)
        asm volatile(
            "ldmatrix.sync.aligned.m8n8.x4.shared.b16 {%0,%1,%2,%3}, [%4];"
            : "=r"(fr[ng][0]), "=r"(fr[ng][1]), "=r"(fr[ng][2]), "=r"(fr[ng][3])
            : "r"(Bb + boff + (uint32_t)ng * (16u * PITCH) + kb));
}

// ---------------------------------------------------------------------------
// Kernel 2: upper-triangular fused sim-exp-rowsum (bf16).
// 528 CTAs; CTA k -> tile (ti, tj), tj >= ti, 128x128 per tile.
// 8 warps (2x4), warp tile 64x32. 8 K-stages of 64 bf16 (128B/row),
// pitch 144, double-buffered cp.async, dynamic smem 72KB.
// Fragment regs double-buffered: next-ks LDSM issued before current MMAs.
// ---------------------------------------------------------------------------
__global__ __launch_bounds__(256) void k_simexp() {
    extern __shared__ __align__(128) char dsm[];
    __shared__ float rs_row[128];
    __shared__ float rs_col[128];

    int tid = threadIdx.x;
    int l = tid & 31;
    int wid = tid >> 5;
    int wm = wid >> 2;   // 0..1
    int wn = wid & 3;    // 0..3

    // triangular decode: k -> (ti, tj), start(ti) = 32*ti - ti*(ti-1)/2
    int k = blockIdx.x;
    int ti = (int)((65.0f - sqrtf(4225.0f - 8.0f * (float)k)) * 0.5f);
    while ((ti + 1) * 32 - ((ti + 1) * ti) / 2 <= k) ++ti;
    while (ti * 32 - (ti * (ti - 1)) / 2 > k) --ti;
    int tj = ti + (k - (ti * 32 - (ti * (ti - 1)) / 2));
    int r0 = ti * 128, c0 = tj * 128;
    bool dual = (ti != tj);
    bool postile = (tj - ti) == 16;
    const char* zb = (const char*)g_znh;   // row stride 1024B

    if (tid < 128) { rs_row[tid] = 0.0f; rs_col[tid] = 0.0f; }

    uint32_t sA0 = (uint32_t)__cvta_generic_to_shared(dsm);
    uint32_t sB0 = sA0 + 2u * STG_BYTES;

    uint32_t aoff = (uint32_t)((64 * wm + (l & 15)) * PITCH + ((l >> 4) & 1) * 16);
    uint32_t boff = (uint32_t)((32 * wn + (l & 7) + ((l >> 4) & 1) * 8) * PITCH
                               + ((l >> 3) & 1) * 16);

    float acc[4][4][4];
#pragma unroll
    for (int a = 0; a < 4; ++a)
#pragma unroll
        for (int b = 0; b < 4; ++b)
#pragma unroll
            for (int d = 0; d < 4; ++d) acc[a][b][d] = 0.0f;

    auto load_stage = [&](int s) {
        uint32_t koff = (uint32_t)s * 128u;  // 64 bf16 per stage
#pragma unroll
        for (int m = 0; m < 8; ++m) {
            int ch = tid + m * 256;          // 0..2047 16B chunks
            int half = ch >> 10;             // 0=A, 1=B
            int e = ch & 1023;
            int row = e >> 3, seg = e & 7;
            uint32_t dst = (half ? sB0 : sA0)
                         + (uint32_t)(s & 1) * (uint32_t)STG_BYTES
                         + (uint32_t)row * PITCH + (uint32_t)seg * 16u;
            const char* src = zb + (size_t)((half ? c0 : r0) + row) * 1024u
                            + koff + (uint32_t)seg * 16u;
            asm volatile("cp.async.cg.shared.global [%0], [%1], 16;"
                         :: "r"(dst), "l"(src) : "memory");
        }
        asm volatile("cp.async.commit_group;" ::: "memory");
    };

    load_stage(0);
    for (int s = 0; s < 8; ++s) {
        if (s + 1 < 8) {
            load_stage(s + 1);
            asm volatile("cp.async.wait_group 1;" ::: "memory");
        } else {
            asm volatile("cp.async.wait_group 0;" ::: "memory");
        }
        __syncthreads();

        uint32_t Ab = sA0 + (uint32_t)(s & 1) * (uint32_t)STG_BYTES;
        uint32_t Bb = sB0 + (uint32_t)(s & 1) * (uint32_t)STG_BYTES;

        uint32_t af[2][4][4], bf[2][2][4];
        ldsm_a(af[0], Ab, aoff, 0u);
        ldsm_b(bf[0], Bb, boff, 0u);
#pragma unroll
        for (int ks = 0; ks < 4; ++ks) {
            const int cur = ks & 1;
            const int nxt = cur ^ 1;
            if (ks < 3) {   // prefetch next-ks fragments BEFORE the MMA burst
                uint32_t kb = (uint32_t)(ks + 1) * 32u;
                ldsm_a(af[nxt], Ab, aoff, kb);
                ldsm_b(bf[nxt], Bb, boff, kb);
            }
#pragma unroll
            for (int mt = 0; mt < 4; ++mt)
#pragma unroll
                for (int nt = 0; nt < 4; ++nt) {
                    uint32_t b0 = bf[cur][nt >> 1][(nt & 1) * 2];
                    uint32_t b1 = bf[cur][nt >> 1][(nt & 1) * 2 + 1];
                    asm volatile(
                        "mma.sync.aligned.m16n8k16.row.col.f32.bf16.bf16.f32 "
                        "{%0,%1,%2,%3}, {%4,%5,%6,%7}, {%8,%9}, {%0,%1,%2,%3};"
                        : "+f"(acc[mt][nt][0]), "+f"(acc[mt][nt][1]),
                          "+f"(acc[mt][nt][2]), "+f"(acc[mt][nt][3])
                        : "r"(af[cur][mt][0]), "r"(af[cur][mt][1]),
                          "r"(af[cur][mt][2]), "r"(af[cur][mt][3]),
                          "r"(b0), "r"(b1));
                }
        }
        __syncthreads();
    }

    // Epilogue. D row = 64wm + 16mt + (l>>2) + 8*half ; col = 32wn + 8nt + (l&3)*2.
    float vcol[4][2];
#pragma unroll
    for (int nt = 0; nt < 4; ++nt) { vcol[nt][0] = 0.0f; vcol[nt][1] = 0.0f; }

#pragma unroll
    for (int mt = 0; mt < 4; ++mt) {
#pragma unroll
        for (int half = 0; half < 2; ++half) {
            int rl = 64 * wm + 16 * mt + (l >> 2) + 8 * half;
            int gr = r0 + rl;
            float v = 0.0f;
#pragma unroll
            for (int nt = 0; nt < 4; ++nt) {
                int gc = c0 + 32 * wn + 8 * nt + (l & 3) * 2;
                float d0 = acc[mt][nt][half * 2 + 0];
                float d1 = acc[mt][nt][half * 2 + 1];
                float e0 = exp_sim(d0);
                float e1 = exp_sim(d1);
                if (postile) {   // positive-pair diagonal lives in these tiles
                    if (gc == gr + Bz)     { g_pos[gr] = d0; g_pos[gc] = d0; }
                    if (gc + 1 == gr + Bz) { g_pos[gr] = d1; g_pos[gc + 1] = d1; }
                }
                v += (gr == gc) ? 0.0f : e0;
                v += (gr == gc + 1) ? 0.0f : e1;
                vcol[nt][0] += e0;
                vcol[nt][1] += e1;
            }
            v += __shfl_xor_sync(0xffffffffu, v, 1);
            v += __shfl_xor_sync(0xffffffffu, v, 2);
            if ((l & 3) == 0) atomicAdd(&rs_row[rl], v);
        }
    }
    if (dual) {
#pragma unroll
        for (int nt = 0; nt < 4; ++nt) {
            float cv0 = vcol[nt][0], cv1 = vcol[nt][1];
#pragma unroll
            for (int o = 4; o <= 16; o <<= 1) {
                cv0 += __shfl_xor_sync(0xffffffffu, cv0, o);
                cv1 += __shfl_xor_sync(0xffffffffu, cv1, o);
            }
            if ((l >> 2) == 0) {
                int cl = 32 * wn + 8 * nt + (l & 3) * 2;
                atomicAdd(&rs_col[cl], cv0);
                atomicAdd(&rs_col[cl + 1], cv1);
            }
        }
    }
    __syncthreads();
    if (tid < 128) {
        atomicAdd(&g_rowsum[r0 + tid], rs_row[tid]);
        if (dual) atomicAdd(&g_rowsum[c0 + tid], rs_col[tid]);
    }
}

// ---------------------------------------------------------------------------
// Kernel 3: finalize. loss_i = 2 + log(rowsum_i) - 2*pos_i ; mean into out.
// ---------------------------------------------------------------------------
__global__ void k_finalize(float* __restrict__ out) {
    int i = blockIdx.x * 256 + threadIdx.x;
    float term = 2.0f + logf(g_rowsum[i]) - 2.0f * g_pos[i];
    int l = threadIdx.x & 31;
#pragma unroll
    for (int o = 16; o > 0; o >>= 1) term += __shfl_xor_sync(0xffffffffu, term, o);
    __shared__ float red[8];
    if (l == 0) red[threadIdx.x >> 5] = term;
    __syncthreads();
    if (threadIdx.x == 0) {
        float s = 0.0f;
#pragma unroll
        for (int w = 0; w < 8; ++w) s += red[w];
        atomicAdd(out, s * (1.0f / (float)Nn));
    }
}

extern "C" void kernel_launch(void* const* d_in, const int* in_sizes, int n_in,
                              void* d_out, int out_size) {
    const float* zi = (const float*)d_in[0];
    const float* zj = (const float*)d_in[1];
    float* out = (float*)d_out;

    cudaFuncSetAttribute(k_simexp, cudaFuncAttributeMaxDynamicSharedMemorySize,
                         SMEM_TOTAL);

    k_normalize<<<Nn / 16, 256>>>(zi, zj, out);
    k_simexp<<<NTILE, 256, SMEM_TOTAL>>>();
    k_finalize<<<Nn / 256, 256>>>(out);
}